// round 15
// baseline (speedup 1.0000x reference)
#include <cuda_runtime.h>
#include <cuda_bf16.h>
#include <cuda_fp16.h>
#include <cstdint>

// SelfAttention: B=4, N=4096, C=F=128. out = softmax(QK^T)V + x.
// Round 14: (1) attn at 3 CTAs/SM (launch_bounds(128,3), 12 warps/SM) -- clean
// occupancy test on the unchanged R13 loop. (2) log2(e) folded into Q so
// exp() becomes a bare ex2.approx (no FMUL in the softmax chain).

#define NB 4
#define NN 4096
#define NC 128
#define BQ 64
#define BK 64
#define NIT (NN / BK)   // 64
#define LOG2E 1.4426950408889634f

// ---------------- device globals (no cudaMalloc allowed) -------------------
__device__ __half        g_q16[(size_t)NB * NN * NC];   // Q fp16 (pre-scaled by log2e)
__device__ __half        g_k16[(size_t)NB * NN * NC];   // K fp16
__device__ __half        g_vt [(size_t)NB * NC * NN];   // V^T fp16 [b][f][n]
__device__ __nv_bfloat16 g_wthi[3 * 128 * 128];         // W^T hi [p][n][k]
__device__ __nv_bfloat16 g_wtlo[3 * 128 * 128];         // W^T lo

// ---------------- attn smem (bytes, per buffer) ------------------------------
// KH[64][136]f16 (17408) + VT[128][72]f16 (18432) = 35840/buffer, x2 = 71680.
#define KROW 272
#define VROW 144
#define OFF_KHI 0
#define OFF_VT  17408
#define BUF_SZ  35840
#define ATTN_SMEM (2 * BUF_SZ)   // 71680 -> 3 CTAs/SM (215040 <= 233472)

// ---------------- qkv smem ----------------------------------------------------
#define QKV_XH 0u
#define QKV_XL 17408u
#define QKV_WH 34816u
#define QKV_WL 69632u
#define QKV_SMEM 104448

extern __shared__ __align__(16) char smem_raw[];

// ---------------- helpers ----------------------------------------------------
__device__ __forceinline__ uint32_t smem_u32(const void* p) {
    uint32_t a;
    asm("{ .reg .u64 t; cvta.to.shared.u64 t, %1; cvt.u32.u64 %0, t; }"
        : "=r"(a) : "l"(p));
    return a;
}
__device__ __forceinline__ float ex2f(float x) {
    float r;
    asm("ex2.approx.f32 %0, %1;" : "=f"(r) : "f"(x));
    return r;
}
__device__ __forceinline__ void cp16(uint32_t dst, const void* src) {
    asm volatile("cp.async.cg.shared.global [%0], [%1], 16;"
                 :: "r"(dst), "l"(src) : "memory");
}
__device__ __forceinline__ void cp_commit() {
    asm volatile("cp.async.commit_group;" ::: "memory");
}
template<int N> __device__ __forceinline__ void cp_wait() {
    asm volatile("cp.async.wait_group %0;" :: "n"(N) : "memory");
}
__device__ __forceinline__ void ldsm4(uint32_t& r0, uint32_t& r1,
                                      uint32_t& r2, uint32_t& r3, uint32_t a) {
    asm volatile("ldmatrix.sync.aligned.m8n8.x4.shared.b16 {%0,%1,%2,%3}, [%4];"
                 : "=r"(r0), "=r"(r1), "=r"(r2), "=r"(r3) : "r"(a));
}
__device__ __forceinline__ void mma_bf16(float* d, const uint32_t* a,
                                         uint32_t b0, uint32_t b1) {
    asm volatile(
        "mma.sync.aligned.m16n8k16.row.col.f32.bf16.bf16.f32 "
        "{%0,%1,%2,%3}, {%4,%5,%6,%7}, {%8,%9}, {%0,%1,%2,%3};"
        : "+f"(d[0]), "+f"(d[1]), "+f"(d[2]), "+f"(d[3])
        : "r"(a[0]), "r"(a[1]), "r"(a[2]), "r"(a[3]), "r"(b0), "r"(b1));
}
__device__ __forceinline__ void mma_f16(float* d, const uint32_t* a,
                                        uint32_t b0, uint32_t b1) {
    asm volatile(
        "mma.sync.aligned.m16n8k16.row.col.f32.f16.f16.f32 "
        "{%0,%1,%2,%3}, {%4,%5,%6,%7}, {%8,%9}, {%0,%1,%2,%3};"
        : "+f"(d[0]), "+f"(d[1]), "+f"(d[2]), "+f"(d[3])
        : "r"(a[0]), "r"(a[1]), "r"(a[2]), "r"(a[3]), "r"(b0), "r"(b1));
}

// ---------------------------------------------------------------------------
// W pre-split: W[p][k][n] fp32 -> W^T hi/lo bf16 [p][n][k]. 192 CTAs x 256 thr.
// ---------------------------------------------------------------------------
__global__ void split_w(const float* __restrict__ Wq,
                        const float* __restrict__ Wk,
                        const float* __restrict__ Wv)
{
    const float* Ws[3] = {Wq, Wk, Wv};
    int idx = blockIdx.x * 256 + threadIdx.x;   // 0..49151
    int p = idx >> 14, r = idx & 16383;
    int n = r >> 7, k = r & 127;
    float v = Ws[p][k * 128 + n];
    __nv_bfloat16 h = __float2bfloat16(v);
    g_wthi[idx] = h;
    g_wtlo[idx] = __float2bfloat16(v - __bfloat162float(h));
}

// ---------------------------------------------------------------------------
// QKV projection on tensor cores. 256 CTAs x 128 thr (4 warps, 16 rows each).
// 3-pass split-bf16 with pre-split W. Emits Q fp16 (scaled log2e), K fp16,
// V^T fp16 (staged through smem for coalesced stores).
// ---------------------------------------------------------------------------
__global__ __launch_bounds__(128, 2) void qkv_mma(
    const float* __restrict__ x,
    const float* __restrict__ bq, const float* __restrict__ bk,
    const float* __restrict__ bv)
{
    char* smc = smem_raw;
    const uint32_t sb = smem_u32(smc);
    const int tid  = threadIdx.x;
    const int warp = tid >> 5, lane = tid & 31;
    const int g    = lane >> 2, tig = lane & 3;
    const int row0 = blockIdx.x * 64;
    const int lm_row = ((lane >> 4) << 3) + (lane & 7);
    const int lm_col = ((lane >> 3) & 1) * 16;

    __nv_bfloat16* sxh = reinterpret_cast<__nv_bfloat16*>(smc + QKV_XH);
    __nv_bfloat16* sxl = reinterpret_cast<__nv_bfloat16*>(smc + QKV_XL);

    // prefetch W^T hi/lo for p=0
    #pragma unroll
    for (int i = 0; i < 16; i++) {
        int idx = tid + i * 128;
        int r = idx >> 4, q = idx & 15;
        cp16(sb + QKV_WH + r * 272 + q * 16, g_wthi + (size_t)r * 128 + q * 8);
        cp16(sb + QKV_WL + r * 272 + q * 16, g_wtlo + (size_t)r * 128 + q * 8);
    }
    cp_commit();

    // x tile -> hi/lo bf16 splits in smem
    #pragma unroll
    for (int i = 0; i < 64; i++) {
        int idx = tid + i * 128;
        int r = idx >> 7, c = idx & 127;
        float v = x[(size_t)row0 * 128 + idx];
        __nv_bfloat16 h = __float2bfloat16(v);
        sxh[r * 136 + c] = h;
        sxl[r * 136 + c] = __float2bfloat16(v - __bfloat162float(h));
    }
    __syncthreads();

    // A fragments (16 rows per warp)
    uint32_t xh[8][4], xl[8][4];
    #pragma unroll
    for (int ks = 0; ks < 8; ks++) {
        int c2 = (ks * 16 + tig * 2) * 2;
        int ra = (warp * 16 + g) * 272, rb = (warp * 16 + g + 8) * 272;
        xh[ks][0] = *(const uint32_t*)(smc + QKV_XH + ra + c2);
        xh[ks][1] = *(const uint32_t*)(smc + QKV_XH + rb + c2);
        xh[ks][2] = *(const uint32_t*)(smc + QKV_XH + ra + c2 + 16);
        xh[ks][3] = *(const uint32_t*)(smc + QKV_XH + rb + c2 + 16);
        xl[ks][0] = *(const uint32_t*)(smc + QKV_XL + ra + c2);
        xl[ks][1] = *(const uint32_t*)(smc + QKV_XL + rb + c2);
        xl[ks][2] = *(const uint32_t*)(smc + QKV_XL + ra + c2 + 16);
        xl[ks][3] = *(const uint32_t*)(smc + QKV_XL + rb + c2 + 16);
    }

    const float* Bs[3] = {bq, bk, bv};

    for (int p = 0; p < 3; p++) {
        cp_wait<0>();
        __syncthreads();

        float acc[16][4];
        #pragma unroll
        for (int nb = 0; nb < 16; nb++)
            #pragma unroll
            for (int j = 0; j < 4; j++) acc[nb][j] = 0.f;

        #pragma unroll
        for (int ks = 0; ks < 8; ks++) {
            #pragma unroll
            for (int nbp = 0; nbp < 8; nbp++) {
                uint32_t a = sb + QKV_WH + (uint32_t)(nbp * 16 + lm_row) * 272
                           + ks * 32 + lm_col;
                uint32_t h0, h1, h2, h3, l0_, l1_, l2_, l3_;
                ldsm4(h0, h1, h2, h3, a);
                ldsm4(l0_, l1_, l2_, l3_, a + (QKV_WL - QKV_WH));
                mma_bf16(acc[2*nbp],   xh[ks], h0, h1);
                mma_bf16(acc[2*nbp],   xh[ks], l0_, l1_);
                mma_bf16(acc[2*nbp],   xl[ks], h0, h1);
                mma_bf16(acc[2*nbp+1], xh[ks], h2, h3);
                mma_bf16(acc[2*nbp+1], xh[ks], l2_, l3_);
                mma_bf16(acc[2*nbp+1], xl[ks], h2, h3);
            }
        }

        __syncthreads();   // readers done before overwriting W smem / X region
        if (p < 2) {
            const __nv_bfloat16* wh = g_wthi + (size_t)(p + 1) * 16384;
            const __nv_bfloat16* wl = g_wtlo + (size_t)(p + 1) * 16384;
            #pragma unroll
            for (int i = 0; i < 16; i++) {
                int idx = tid + i * 128;
                int r = idx >> 4, q = idx & 15;
                cp16(sb + QKV_WH + r * 272 + q * 16, wh + (size_t)r * 128 + q * 8);
                cp16(sb + QKV_WL + r * 272 + q * 16, wl + (size_t)r * 128 + q * 8);
            }
            cp_commit();
        }

        const float* bp = Bs[p];
        const int t0 = row0 + warp * 16 + g;
        if (p < 2) {
            __half* dst = (p == 0) ? g_q16 : g_k16;
            const float sc = (p == 0) ? LOG2E : 1.0f;   // fold log2e into Q
            #pragma unroll
            for (int nb = 0; nb < 16; nb++) {
                int col = nb * 8 + tig * 2;
                float2 bb = *(const float2*)(bp + col);
                __half2 a2;
                a2.x = __float2half_rn((acc[nb][0] + bb.x) * sc);
                a2.y = __float2half_rn((acc[nb][1] + bb.y) * sc);
                __half2 b2;
                b2.x = __float2half_rn((acc[nb][2] + bb.x) * sc);
                b2.y = __float2half_rn((acc[nb][3] + bb.y) * sc);
                *reinterpret_cast<__half2*>(dst + (size_t)t0 * 128 + col) = a2;
                *reinterpret_cast<__half2*>(dst + (size_t)(t0 + 8) * 128 + col) = b2;
            }
        } else {
            // ---- V: stage V^T tile [128 f][64 tokens] in smem (X region free)
            __half* vst = reinterpret_cast<__half*>(smc);
            const int tl = warp * 16 + g;
            #pragma unroll
            for (int nb = 0; nb < 16; nb++) {
                int col = nb * 8 + tig * 2;
                float2 bb = *(const float2*)(bp + col);
                vst[col * 64 + tl]           = __float2half_rn(acc[nb][0] + bb.x);
                vst[(col + 1) * 64 + tl]     = __float2half_rn(acc[nb][1] + bb.y);
                vst[col * 64 + tl + 8]       = __float2half_rn(acc[nb][2] + bb.x);
                vst[(col + 1) * 64 + tl + 8] = __float2half_rn(acc[nb][3] + bb.y);
            }
            __syncthreads();
            // coalesced copy-out: 1024 chunks of 16B
            const int b_ = row0 >> 12, n0 = row0 & 4095;
            #pragma unroll
            for (int i = 0; i < 8; i++) {
                int c = tid + i * 128;
                int f = c >> 3, q = c & 7;
                uint4 v = *reinterpret_cast<uint4*>(vst + f * 64 + q * 8);
                *reinterpret_cast<uint4*>(
                    g_vt + ((size_t)b_ * 128 + f) * 4096 + n0 + q * 8) = v;
            }
        }
    }
}

// ---------------------------------------------------------------------------
// attn tile loader (128 threads): KH [64][136]f16 + Vt [128][72]f16.
// ---------------------------------------------------------------------------
__device__ __forceinline__ void load_tiles(uint32_t dstb, int tid,
    const __half* kb_, const __half* vtb, int kt)
{
    const int k0 = kt * BK;
    #pragma unroll
    for (int i = 0; i < 8; i++) {
        int idx = tid + i * 128;           // 0..1023
        int row = idx >> 4, q = idx & 15;  // 64 rows x 16 chunks
        cp16(dstb + OFF_KHI + row * KROW + q * 16,
             kb_ + (size_t)(k0 + row) * NC + q * 8);
    }
    #pragma unroll
    for (int i = 0; i < 8; i++) {
        int idx = tid + i * 128;           // 0..1023
        int row = idx >> 3, q = idx & 7;   // 128 rows x 8 chunks
        cp16(dstb + OFF_VT + row * VROW + q * 16,
             vtb + (size_t)row * NN + k0 + q * 8);
    }
    cp_commit();
}

// ---------------------------------------------------------------------------
// Flash attention (R13 loop, 3 CTAs/SM). 256 CTAs, 128 thr.
// S = q16*k16 (logits already in log2 domain); exp = bare ex2.approx.
// ---------------------------------------------------------------------------
__global__ __launch_bounds__(128, 3) void attn_mma(
    const float* __restrict__ x, float* __restrict__ out)
{
    char* smc = smem_raw;
    const uint32_t sb = smem_u32(smc);
    const int tid  = threadIdx.x;
    const int warp = tid >> 5, lane = tid & 31;
    const int g    = lane >> 2, tig = lane & 3;
    const int b    = blockIdx.x >> 6;
    const int q0   = (blockIdx.x & 63) * BQ;
    const int qrow = q0 + warp * 16;
    const int lm_row = ((lane >> 4) << 3) + (lane & 7);
    const int lm_col = ((lane >> 3) & 1) * 16;

    // Q fragments (fp16, pre-scaled), loaded once from global
    uint32_t qh[8][4];
    {
        const uint16_t* qp = (const uint16_t*)g_q16 + ((size_t)b * NN + qrow) * NC;
        #pragma unroll
        for (int ks = 0; ks < 8; ks++) {
            int c = ks * 16 + tig * 2;
            qh[ks][0] = *(const uint32_t*)(qp + (size_t)g * NC + c);
            qh[ks][1] = *(const uint32_t*)(qp + (size_t)(g + 8) * NC + c);
            qh[ks][2] = *(const uint32_t*)(qp + (size_t)g * NC + c + 8);
            qh[ks][3] = *(const uint32_t*)(qp + (size_t)(g + 8) * NC + c + 8);
        }
    }

    const __half* kb_ = g_k16 + (size_t)b * NN * NC;
    const __half* vtb = g_vt  + (size_t)b * NC * NN;

    float O[16][4];
    #pragma unroll
    for (int n = 0; n < 16; n++)
        #pragma unroll
        for (int j = 0; j < 4; j++) O[n][j] = 0.f;
    float m0 = -1e30f, m1 = -1e30f, l0 = 0.f, l1 = 0.f;

    load_tiles(sb, tid, kb_, vtb, 0);

    for (int kt = 0; kt < NIT; kt++) {
        const int cur = kt & 1;
        if (kt + 1 < NIT) {
            load_tiles(sb + (cur ^ 1) * BUF_SZ, tid, kb_, vtb, kt + 1);
            cp_wait<1>();
        } else {
            cp_wait<0>();
        }
        __syncthreads();

        const uint32_t kb = sb + cur * BUF_SZ;

        // ---- S = q16 * k16 : single pass fp16, ldmatrix B-frags ----
        float s[8][4];
        #pragma unroll
        for (int n = 0; n < 8; n++)
            #pragma unroll
            for (int j = 0; j < 4; j++) s[n][j] = 0.f;

        #pragma unroll
        for (int ks = 0; ks < 8; ks++) {
            #pragma unroll
            for (int nbp = 0; nbp < 4; nbp++) {
                uint32_t a = kb + (uint32_t)(nbp * 16 + lm_row) * KROW
                           + ks * 32 + lm_col;
                uint32_t h0, h1, h2, h3;
                ldsm4(h0, h1, h2, h3, a);
                mma_f16(s[2*nbp],   qh[ks], h0, h1);
                mma_f16(s[2*nbp+1], qh[ks], h2, h3);
            }
        }

        // ---- online softmax (log2 domain) ----
        float mx0 = -1e30f, mx1 = -1e30f;
        #pragma unroll
        for (int nb = 0; nb < 8; nb++) {
            mx0 = fmaxf(mx0, fmaxf(s[nb][0], s[nb][1]));
            mx1 = fmaxf(mx1, fmaxf(s[nb][2], s[nb][3]));
        }
        mx0 = fmaxf(mx0, __shfl_xor_sync(0xffffffffu, mx0, 1));
        mx0 = fmaxf(mx0, __shfl_xor_sync(0xffffffffu, mx0, 2));
        mx1 = fmaxf(mx1, __shfl_xor_sync(0xffffffffu, mx1, 1));
        mx1 = fmaxf(mx1, __shfl_xor_sync(0xffffffffu, mx1, 2));

        if (mx0 > m0 || mx1 > m1) {           // conditional rescale
            float mn0 = fmaxf(m0, mx0), mn1 = fmaxf(m1, mx1);
            float sc0 = ex2f(m0 - mn0), sc1 = ex2f(m1 - mn1);
            m0 = mn0; m1 = mn1;
            l0 *= sc0; l1 *= sc1;
            #pragma unroll
            for (int n = 0; n < 16; n++) {
                O[n][0] *= sc0; O[n][1] *= sc0;
                O[n][2] *= sc1; O[n][3] *= sc1;
            }
        }

        // ---- P = 2^(S-m) -> fp16 A-fragments; l from ROUNDED p ----
        uint32_t pf[4][4];
        #pragma unroll
        for (int kk = 0; kk < 4; kk++) {
            #pragma unroll
            for (int h = 0; h < 2; h++) {
                int nb = 2 * kk + h;
                __half2 ha = __floats2half2_rn(ex2f(s[nb][0] - m0),
                                               ex2f(s[nb][1] - m0));
                __half2 hb = __floats2half2_rn(ex2f(s[nb][2] - m1),
                                               ex2f(s[nb][3] - m1));
                float2 fa = __half22float2(ha);
                float2 fb = __half22float2(hb);
                l0 += fa.x + fa.y;
                l1 += fb.x + fb.y;
                pf[kk][0 + h * 2] = *reinterpret_cast<uint32_t*>(&ha);
                pf[kk][1 + h * 2] = *reinterpret_cast<uint32_t*>(&hb);
            }
        }

        // ---- O += P V (fp16), ldmatrix B-frags ----
        const uint32_t vb = kb + OFF_VT;
        #pragma unroll
        for (int kk = 0; kk < 4; kk++) {
            #pragma unroll
            for (int fp = 0; fp < 8; fp++) {
                uint32_t a = vb + (uint32_t)(fp * 16 + lm_row) * VROW
                           + kk * 32 + lm_col;
                uint32_t v0, v1, v2, v3;
                ldsm4(v0, v1, v2, v3, a);
                mma_f16(O[2*fp],   pf[kk], v0, v1);
                mma_f16(O[2*fp+1], pf[kk], v2, v3);
            }
        }
        __syncthreads();
    }

    // ---- epilogue: reduce l over quad, normalize, add residual ----
    l0 += __shfl_xor_sync(0xffffffffu, l0, 1);
    l0 += __shfl_xor_sync(0xffffffffu, l0, 2);
    l1 += __shfl_xor_sync(0xffffffffu, l1, 1);
    l1 += __shfl_xor_sync(0xffffffffu, l1, 2);
    const float inv0 = 1.f / l0, inv1 = 1.f / l1;

    const size_t ra = ((size_t)b * NN + qrow + g) * NC;
    const size_t rb = ((size_t)b * NN + qrow + g + 8) * NC;
    #pragma unroll
    for (int nb2 = 0; nb2 < 16; nb2++) {
        int col = nb2 * 8 + tig * 2;
        float2 xa = *(const float2*)(x + ra + col);
        float2 xb = *(const float2*)(x + rb + col);
        float2 oa = { O[nb2][0] * inv0 + xa.x, O[nb2][1] * inv0 + xa.y };
        float2 ob = { O[nb2][2] * inv1 + xb.x, O[nb2][3] * inv1 + xb.y };
        *(float2*)(out + ra + col) = oa;
        *(float2*)(out + rb + col) = ob;
    }
}

// ---------------------------------------------------------------------------
extern "C" void kernel_launch(void* const* d_in, const int* in_sizes, int n_in,
                              void* d_out, int out_size)
{
    (void)in_sizes; (void)n_in; (void)out_size;
    const float* x  = (const float*)d_in[0];
    const float* Wq = (const float*)d_in[1];
    const float* bq = (const float*)d_in[2];
    const float* Wk = (const float*)d_in[3];
    const float* bk = (const float*)d_in[4];
    const float* Wv = (const float*)d_in[5];
    const float* bv = (const float*)d_in[6];
    float* out = (float*)d_out;

    cudaFuncSetAttribute(qkv_mma,  cudaFuncAttributeMaxDynamicSharedMemorySize, QKV_SMEM);
    cudaFuncSetAttribute(attn_mma, cudaFuncAttributeMaxDynamicSharedMemorySize, ATTN_SMEM);

    split_w<<<192, 256>>>(Wq, Wk, Wv);
    qkv_mma<<<(NB * NN) / 64, 128, QKV_SMEM>>>(x, bq, bk, bv);
    attn_mma<<<NB * (NN / BQ), 128, ATTN_SMEM>>>(x, out);
}

// round 16
// speedup vs baseline: 1.1490x; 1.1490x over previous
#include <cuda_runtime.h>
#include <cuda_bf16.h>
#include <cuda_fp16.h>
#include <cstdint>

// SelfAttention: B=4, N=4096, C=F=128. out = softmax(QK^T)V + x.
// Round 15: R13 config (launch_bounds(128,2) — 3-CTA occupancy triply rejected:
// reg wall at ~190-230 regs), KEEPING R14's log2e-folded-Q + bare ex2.approx
// softmax (shorter serial chain, fewer live temps).

#define NB 4
#define NN 4096
#define NC 128
#define BQ 64
#define BK 64
#define NIT (NN / BK)   // 64
#define LOG2E 1.4426950408889634f

// ---------------- device globals (no cudaMalloc allowed) -------------------
__device__ __half        g_q16[(size_t)NB * NN * NC];   // Q fp16 (pre-scaled by log2e)
__device__ __half        g_k16[(size_t)NB * NN * NC];   // K fp16
__device__ __half        g_vt [(size_t)NB * NC * NN];   // V^T fp16 [b][f][n]
__device__ __nv_bfloat16 g_wthi[3 * 128 * 128];         // W^T hi [p][n][k]
__device__ __nv_bfloat16 g_wtlo[3 * 128 * 128];         // W^T lo

// ---------------- attn smem (bytes, per buffer) ------------------------------
// KH[64][136]f16 (17408) + VT[128][72]f16 (18432) = 35840/buffer, x2 = 71680.
#define KROW 272
#define VROW 144
#define OFF_KHI 0
#define OFF_VT  17408
#define BUF_SZ  35840
#define ATTN_SMEM (2 * BUF_SZ)   // 71680

// ---------------- qkv smem ----------------------------------------------------
#define QKV_XH 0u
#define QKV_XL 17408u
#define QKV_WH 34816u
#define QKV_WL 69632u
#define QKV_SMEM 104448

extern __shared__ __align__(16) char smem_raw[];

// ---------------- helpers ----------------------------------------------------
__device__ __forceinline__ uint32_t smem_u32(const void* p) {
    uint32_t a;
    asm("{ .reg .u64 t; cvta.to.shared.u64 t, %1; cvt.u32.u64 %0, t; }"
        : "=r"(a) : "l"(p));
    return a;
}
__device__ __forceinline__ float ex2f(float x) {
    float r;
    asm("ex2.approx.f32 %0, %1;" : "=f"(r) : "f"(x));
    return r;
}
__device__ __forceinline__ void cp16(uint32_t dst, const void* src) {
    asm volatile("cp.async.cg.shared.global [%0], [%1], 16;"
                 :: "r"(dst), "l"(src) : "memory");
}
__device__ __forceinline__ void cp_commit() {
    asm volatile("cp.async.commit_group;" ::: "memory");
}
template<int N> __device__ __forceinline__ void cp_wait() {
    asm volatile("cp.async.wait_group %0;" :: "n"(N) : "memory");
}
__device__ __forceinline__ void ldsm4(uint32_t& r0, uint32_t& r1,
                                      uint32_t& r2, uint32_t& r3, uint32_t a) {
    asm volatile("ldmatrix.sync.aligned.m8n8.x4.shared.b16 {%0,%1,%2,%3}, [%4];"
                 : "=r"(r0), "=r"(r1), "=r"(r2), "=r"(r3) : "r"(a));
}
__device__ __forceinline__ void mma_bf16(float* d, const uint32_t* a,
                                         uint32_t b0, uint32_t b1) {
    asm volatile(
        "mma.sync.aligned.m16n8k16.row.col.f32.bf16.bf16.f32 "
        "{%0,%1,%2,%3}, {%4,%5,%6,%7}, {%8,%9}, {%0,%1,%2,%3};"
        : "+f"(d[0]), "+f"(d[1]), "+f"(d[2]), "+f"(d[3])
        : "r"(a[0]), "r"(a[1]), "r"(a[2]), "r"(a[3]), "r"(b0), "r"(b1));
}
__device__ __forceinline__ void mma_f16(float* d, const uint32_t* a,
                                        uint32_t b0, uint32_t b1) {
    asm volatile(
        "mma.sync.aligned.m16n8k16.row.col.f32.f16.f16.f32 "
        "{%0,%1,%2,%3}, {%4,%5,%6,%7}, {%8,%9}, {%0,%1,%2,%3};"
        : "+f"(d[0]), "+f"(d[1]), "+f"(d[2]), "+f"(d[3])
        : "r"(a[0]), "r"(a[1]), "r"(a[2]), "r"(a[3]), "r"(b0), "r"(b1));
}

// ---------------------------------------------------------------------------
// W pre-split: W[p][k][n] fp32 -> W^T hi/lo bf16 [p][n][k]. 192 CTAs x 256 thr.
// ---------------------------------------------------------------------------
__global__ void split_w(const float* __restrict__ Wq,
                        const float* __restrict__ Wk,
                        const float* __restrict__ Wv)
{
    const float* Ws[3] = {Wq, Wk, Wv};
    int idx = blockIdx.x * 256 + threadIdx.x;   // 0..49151
    int p = idx >> 14, r = idx & 16383;
    int n = r >> 7, k = r & 127;
    float v = Ws[p][k * 128 + n];
    __nv_bfloat16 h = __float2bfloat16(v);
    g_wthi[idx] = h;
    g_wtlo[idx] = __float2bfloat16(v - __bfloat162float(h));
}

// ---------------------------------------------------------------------------
// QKV projection on tensor cores. 256 CTAs x 128 thr (4 warps, 16 rows each).
// 3-pass split-bf16 with pre-split W. Emits Q fp16 (scaled log2e), K fp16,
// V^T fp16 (staged through smem for coalesced stores).
// ---------------------------------------------------------------------------
__global__ __launch_bounds__(128, 2) void qkv_mma(
    const float* __restrict__ x,
    const float* __restrict__ bq, const float* __restrict__ bk,
    const float* __restrict__ bv)
{
    char* smc = smem_raw;
    const uint32_t sb = smem_u32(smc);
    const int tid  = threadIdx.x;
    const int warp = tid >> 5, lane = tid & 31;
    const int g    = lane >> 2, tig = lane & 3;
    const int row0 = blockIdx.x * 64;
    const int lm_row = ((lane >> 4) << 3) + (lane & 7);
    const int lm_col = ((lane >> 3) & 1) * 16;

    __nv_bfloat16* sxh = reinterpret_cast<__nv_bfloat16*>(smc + QKV_XH);
    __nv_bfloat16* sxl = reinterpret_cast<__nv_bfloat16*>(smc + QKV_XL);

    // prefetch W^T hi/lo for p=0
    #pragma unroll
    for (int i = 0; i < 16; i++) {
        int idx = tid + i * 128;
        int r = idx >> 4, q = idx & 15;
        cp16(sb + QKV_WH + r * 272 + q * 16, g_wthi + (size_t)r * 128 + q * 8);
        cp16(sb + QKV_WL + r * 272 + q * 16, g_wtlo + (size_t)r * 128 + q * 8);
    }
    cp_commit();

    // x tile -> hi/lo bf16 splits in smem
    #pragma unroll
    for (int i = 0; i < 64; i++) {
        int idx = tid + i * 128;
        int r = idx >> 7, c = idx & 127;
        float v = x[(size_t)row0 * 128 + idx];
        __nv_bfloat16 h = __float2bfloat16(v);
        sxh[r * 136 + c] = h;
        sxl[r * 136 + c] = __float2bfloat16(v - __bfloat162float(h));
    }
    __syncthreads();

    // A fragments (16 rows per warp)
    uint32_t xh[8][4], xl[8][4];
    #pragma unroll
    for (int ks = 0; ks < 8; ks++) {
        int c2 = (ks * 16 + tig * 2) * 2;
        int ra = (warp * 16 + g) * 272, rb = (warp * 16 + g + 8) * 272;
        xh[ks][0] = *(const uint32_t*)(smc + QKV_XH + ra + c2);
        xh[ks][1] = *(const uint32_t*)(smc + QKV_XH + rb + c2);
        xh[ks][2] = *(const uint32_t*)(smc + QKV_XH + ra + c2 + 16);
        xh[ks][3] = *(const uint32_t*)(smc + QKV_XH + rb + c2 + 16);
        xl[ks][0] = *(const uint32_t*)(smc + QKV_XL + ra + c2);
        xl[ks][1] = *(const uint32_t*)(smc + QKV_XL + rb + c2);
        xl[ks][2] = *(const uint32_t*)(smc + QKV_XL + ra + c2 + 16);
        xl[ks][3] = *(const uint32_t*)(smc + QKV_XL + rb + c2 + 16);
    }

    const float* Bs[3] = {bq, bk, bv};

    for (int p = 0; p < 3; p++) {
        cp_wait<0>();
        __syncthreads();

        float acc[16][4];
        #pragma unroll
        for (int nb = 0; nb < 16; nb++)
            #pragma unroll
            for (int j = 0; j < 4; j++) acc[nb][j] = 0.f;

        #pragma unroll
        for (int ks = 0; ks < 8; ks++) {
            #pragma unroll
            for (int nbp = 0; nbp < 8; nbp++) {
                uint32_t a = sb + QKV_WH + (uint32_t)(nbp * 16 + lm_row) * 272
                           + ks * 32 + lm_col;
                uint32_t h0, h1, h2, h3, l0_, l1_, l2_, l3_;
                ldsm4(h0, h1, h2, h3, a);
                ldsm4(l0_, l1_, l2_, l3_, a + (QKV_WL - QKV_WH));
                mma_bf16(acc[2*nbp],   xh[ks], h0, h1);
                mma_bf16(acc[2*nbp],   xh[ks], l0_, l1_);
                mma_bf16(acc[2*nbp],   xl[ks], h0, h1);
                mma_bf16(acc[2*nbp+1], xh[ks], h2, h3);
                mma_bf16(acc[2*nbp+1], xh[ks], l2_, l3_);
                mma_bf16(acc[2*nbp+1], xl[ks], h2, h3);
            }
        }

        __syncthreads();   // readers done before overwriting W smem / X region
        if (p < 2) {
            const __nv_bfloat16* wh = g_wthi + (size_t)(p + 1) * 16384;
            const __nv_bfloat16* wl = g_wtlo + (size_t)(p + 1) * 16384;
            #pragma unroll
            for (int i = 0; i < 16; i++) {
                int idx = tid + i * 128;
                int r = idx >> 4, q = idx & 15;
                cp16(sb + QKV_WH + r * 272 + q * 16, wh + (size_t)r * 128 + q * 8);
                cp16(sb + QKV_WL + r * 272 + q * 16, wl + (size_t)r * 128 + q * 8);
            }
            cp_commit();
        }

        const float* bp = Bs[p];
        const int t0 = row0 + warp * 16 + g;
        if (p < 2) {
            __half* dst = (p == 0) ? g_q16 : g_k16;
            const float sc = (p == 0) ? LOG2E : 1.0f;   // fold log2e into Q
            #pragma unroll
            for (int nb = 0; nb < 16; nb++) {
                int col = nb * 8 + tig * 2;
                float2 bb = *(const float2*)(bp + col);
                __half2 a2;
                a2.x = __float2half_rn((acc[nb][0] + bb.x) * sc);
                a2.y = __float2half_rn((acc[nb][1] + bb.y) * sc);
                __half2 b2;
                b2.x = __float2half_rn((acc[nb][2] + bb.x) * sc);
                b2.y = __float2half_rn((acc[nb][3] + bb.y) * sc);
                *reinterpret_cast<__half2*>(dst + (size_t)t0 * 128 + col) = a2;
                *reinterpret_cast<__half2*>(dst + (size_t)(t0 + 8) * 128 + col) = b2;
            }
        } else {
            // ---- V: stage V^T tile [128 f][64 tokens] in smem (X region free)
            __half* vst = reinterpret_cast<__half*>(smc);
            const int tl = warp * 16 + g;
            #pragma unroll
            for (int nb = 0; nb < 16; nb++) {
                int col = nb * 8 + tig * 2;
                float2 bb = *(const float2*)(bp + col);
                vst[col * 64 + tl]           = __float2half_rn(acc[nb][0] + bb.x);
                vst[(col + 1) * 64 + tl]     = __float2half_rn(acc[nb][1] + bb.y);
                vst[col * 64 + tl + 8]       = __float2half_rn(acc[nb][2] + bb.x);
                vst[(col + 1) * 64 + tl + 8] = __float2half_rn(acc[nb][3] + bb.y);
            }
            __syncthreads();
            // coalesced copy-out: 1024 chunks of 16B
            const int b_ = row0 >> 12, n0 = row0 & 4095;
            #pragma unroll
            for (int i = 0; i < 8; i++) {
                int c = tid + i * 128;
                int f = c >> 3, q = c & 7;
                uint4 v = *reinterpret_cast<uint4*>(vst + f * 64 + q * 8);
                *reinterpret_cast<uint4*>(
                    g_vt + ((size_t)b_ * 128 + f) * 4096 + n0 + q * 8) = v;
            }
        }
    }
}

// ---------------------------------------------------------------------------
// attn tile loader (128 threads): KH [64][136]f16 + Vt [128][72]f16.
// ---------------------------------------------------------------------------
__device__ __forceinline__ void load_tiles(uint32_t dstb, int tid,
    const __half* kb_, const __half* vtb, int kt)
{
    const int k0 = kt * BK;
    #pragma unroll
    for (int i = 0; i < 8; i++) {
        int idx = tid + i * 128;           // 0..1023
        int row = idx >> 4, q = idx & 15;  // 64 rows x 16 chunks
        cp16(dstb + OFF_KHI + row * KROW + q * 16,
             kb_ + (size_t)(k0 + row) * NC + q * 8);
    }
    #pragma unroll
    for (int i = 0; i < 8; i++) {
        int idx = tid + i * 128;           // 0..1023
        int row = idx >> 3, q = idx & 7;   // 128 rows x 8 chunks
        cp16(dstb + OFF_VT + row * VROW + q * 16,
             vtb + (size_t)row * NN + k0 + q * 8);
    }
    cp_commit();
}

// ---------------------------------------------------------------------------
// Flash attention (R13 loop + ex2 softmax). 256 CTAs, 128 thr, 2 CTAs/SM.
// S = q16*k16 (logits already in log2 domain); exp = bare ex2.approx.
// ---------------------------------------------------------------------------
__global__ __launch_bounds__(128, 2) void attn_mma(
    const float* __restrict__ x, float* __restrict__ out)
{
    char* smc = smem_raw;
    const uint32_t sb = smem_u32(smc);
    const int tid  = threadIdx.x;
    const int warp = tid >> 5, lane = tid & 31;
    const int g    = lane >> 2, tig = lane & 3;
    const int b    = blockIdx.x >> 6;
    const int q0   = (blockIdx.x & 63) * BQ;
    const int qrow = q0 + warp * 16;
    const int lm_row = ((lane >> 4) << 3) + (lane & 7);
    const int lm_col = ((lane >> 3) & 1) * 16;

    // Q fragments (fp16, pre-scaled), loaded once from global
    uint32_t qh[8][4];
    {
        const uint16_t* qp = (const uint16_t*)g_q16 + ((size_t)b * NN + qrow) * NC;
        #pragma unroll
        for (int ks = 0; ks < 8; ks++) {
            int c = ks * 16 + tig * 2;
            qh[ks][0] = *(const uint32_t*)(qp + (size_t)g * NC + c);
            qh[ks][1] = *(const uint32_t*)(qp + (size_t)(g + 8) * NC + c);
            qh[ks][2] = *(const uint32_t*)(qp + (size_t)g * NC + c + 8);
            qh[ks][3] = *(const uint32_t*)(qp + (size_t)(g + 8) * NC + c + 8);
        }
    }

    const __half* kb_ = g_k16 + (size_t)b * NN * NC;
    const __half* vtb = g_vt  + (size_t)b * NC * NN;

    float O[16][4];
    #pragma unroll
    for (int n = 0; n < 16; n++)
        #pragma unroll
        for (int j = 0; j < 4; j++) O[n][j] = 0.f;
    float m0 = -1e30f, m1 = -1e30f, l0 = 0.f, l1 = 0.f;

    load_tiles(sb, tid, kb_, vtb, 0);

    for (int kt = 0; kt < NIT; kt++) {
        const int cur = kt & 1;
        if (kt + 1 < NIT) {
            load_tiles(sb + (cur ^ 1) * BUF_SZ, tid, kb_, vtb, kt + 1);
            cp_wait<1>();
        } else {
            cp_wait<0>();
        }
        __syncthreads();

        const uint32_t kb = sb + cur * BUF_SZ;

        // ---- S = q16 * k16 : single pass fp16, ldmatrix B-frags ----
        float s[8][4];
        #pragma unroll
        for (int n = 0; n < 8; n++)
            #pragma unroll
            for (int j = 0; j < 4; j++) s[n][j] = 0.f;

        #pragma unroll
        for (int ks = 0; ks < 8; ks++) {
            #pragma unroll
            for (int nbp = 0; nbp < 4; nbp++) {
                uint32_t a = kb + (uint32_t)(nbp * 16 + lm_row) * KROW
                           + ks * 32 + lm_col;
                uint32_t h0, h1, h2, h3;
                ldsm4(h0, h1, h2, h3, a);
                mma_f16(s[2*nbp],   qh[ks], h0, h1);
                mma_f16(s[2*nbp+1], qh[ks], h2, h3);
            }
        }

        // ---- online softmax (log2 domain) ----
        float mx0 = -1e30f, mx1 = -1e30f;
        #pragma unroll
        for (int nb = 0; nb < 8; nb++) {
            mx0 = fmaxf(mx0, fmaxf(s[nb][0], s[nb][1]));
            mx1 = fmaxf(mx1, fmaxf(s[nb][2], s[nb][3]));
        }
        mx0 = fmaxf(mx0, __shfl_xor_sync(0xffffffffu, mx0, 1));
        mx0 = fmaxf(mx0, __shfl_xor_sync(0xffffffffu, mx0, 2));
        mx1 = fmaxf(mx1, __shfl_xor_sync(0xffffffffu, mx1, 1));
        mx1 = fmaxf(mx1, __shfl_xor_sync(0xffffffffu, mx1, 2));

        if (mx0 > m0 || mx1 > m1) {           // conditional rescale
            float mn0 = fmaxf(m0, mx0), mn1 = fmaxf(m1, mx1);
            float sc0 = ex2f(m0 - mn0), sc1 = ex2f(m1 - mn1);
            m0 = mn0; m1 = mn1;
            l0 *= sc0; l1 *= sc1;
            #pragma unroll
            for (int n = 0; n < 16; n++) {
                O[n][0] *= sc0; O[n][1] *= sc0;
                O[n][2] *= sc1; O[n][3] *= sc1;
            }
        }

        // ---- P = 2^(S-m) -> fp16 A-fragments; l from ROUNDED p ----
        uint32_t pf[4][4];
        #pragma unroll
        for (int kk = 0; kk < 4; kk++) {
            #pragma unroll
            for (int h = 0; h < 2; h++) {
                int nb = 2 * kk + h;
                __half2 ha = __floats2half2_rn(ex2f(s[nb][0] - m0),
                                               ex2f(s[nb][1] - m0));
                __half2 hb = __floats2half2_rn(ex2f(s[nb][2] - m1),
                                               ex2f(s[nb][3] - m1));
                float2 fa = __half22float2(ha);
                float2 fb = __half22float2(hb);
                l0 += fa.x + fa.y;
                l1 += fb.x + fb.y;
                pf[kk][0 + h * 2] = *reinterpret_cast<uint32_t*>(&ha);
                pf[kk][1 + h * 2] = *reinterpret_cast<uint32_t*>(&hb);
            }
        }

        // ---- O += P V (fp16), ldmatrix B-frags ----
        const uint32_t vb = kb + OFF_VT;
        #pragma unroll
        for (int kk = 0; kk < 4; kk++) {
            #pragma unroll
            for (int fp = 0; fp < 8; fp++) {
                uint32_t a = vb + (uint32_t)(fp * 16 + lm_row) * VROW
                           + kk * 32 + lm_col;
                uint32_t v0, v1, v2, v3;
                ldsm4(v0, v1, v2, v3, a);
                mma_f16(O[2*fp],   pf[kk], v0, v1);
                mma_f16(O[2*fp+1], pf[kk], v2, v3);
            }
        }
        __syncthreads();
    }

    // ---- epilogue: reduce l over quad, normalize, add residual ----
    l0 += __shfl_xor_sync(0xffffffffu, l0, 1);
    l0 += __shfl_xor_sync(0xffffffffu, l0, 2);
    l1 += __shfl_xor_sync(0xffffffffu, l1, 1);
    l1 += __shfl_xor_sync(0xffffffffu, l1, 2);
    const float inv0 = 1.f / l0, inv1 = 1.f / l1;

    const size_t ra = ((size_t)b * NN + qrow + g) * NC;
    const size_t rb = ((size_t)b * NN + qrow + g + 8) * NC;
    #pragma unroll
    for (int nb2 = 0; nb2 < 16; nb2++) {
        int col = nb2 * 8 + tig * 2;
        float2 xa = *(const float2*)(x + ra + col);
        float2 xb = *(const float2*)(x + rb + col);
        float2 oa = { O[nb2][0] * inv0 + xa.x, O[nb2][1] * inv0 + xa.y };
        float2 ob = { O[nb2][2] * inv1 + xb.x, O[nb2][3] * inv1 + xb.y };
        *(float2*)(out + ra + col) = oa;
        *(float2*)(out + rb + col) = ob;
    }
}

// ---------------------------------------------------------------------------
extern "C" void kernel_launch(void* const* d_in, const int* in_sizes, int n_in,
                              void* d_out, int out_size)
{
    (void)in_sizes; (void)n_in; (void)out_size;
    const float* x  = (const float*)d_in[0];
    const float* Wq = (const float*)d_in[1];
    const float* bq = (const float*)d_in[2];
    const float* Wk = (const float*)d_in[3];
    const float* bk = (const float*)d_in[4];
    const float* Wv = (const float*)d_in[5];
    const float* bv = (const float*)d_in[6];
    float* out = (float*)d_out;

    cudaFuncSetAttribute(qkv_mma,  cudaFuncAttributeMaxDynamicSharedMemorySize, QKV_SMEM);
    cudaFuncSetAttribute(attn_mma, cudaFuncAttributeMaxDynamicSharedMemorySize, ATTN_SMEM);

    split_w<<<192, 256>>>(Wq, Wk, Wv);
    qkv_mma<<<(NB * NN) / 64, 128, QKV_SMEM>>>(x, bq, bk, bv);
    attn_mma<<<NB * (NN / BQ), 128, ATTN_SMEM>>>(x, out);
}

// round 17
// speedup vs baseline: 1.1685x; 1.0170x over previous
#include <cuda_runtime.h>
#include <cuda_bf16.h>
#include <cuda_fp16.h>
#include <cstdint>

// SelfAttention: B=4, N=4096, C=F=128. out = softmax(QK^T)V + x.
// Round 16: qkv split into 768 CTAs (one projection per CTA) — removes the
// 3-pass serialization; W prefetch hidden under x conversion. Attn = R15 best.

#define NB 4
#define NN 4096
#define NC 128
#define BQ 64
#define BK 64
#define NIT (NN / BK)   // 64
#define LOG2E 1.4426950408889634f

// ---------------- device globals (no cudaMalloc allowed) -------------------
__device__ __half        g_q16[(size_t)NB * NN * NC];   // Q fp16 (pre-scaled by log2e)
__device__ __half        g_k16[(size_t)NB * NN * NC];   // K fp16
__device__ __half        g_vt [(size_t)NB * NC * NN];   // V^T fp16 [b][f][n]
__device__ __nv_bfloat16 g_wthi[3 * 128 * 128];         // W^T hi [p][n][k]
__device__ __nv_bfloat16 g_wtlo[3 * 128 * 128];         // W^T lo

// ---------------- attn smem (bytes, per buffer) ------------------------------
#define KROW 272
#define VROW 144
#define OFF_KHI 0
#define OFF_VT  17408
#define BUF_SZ  35840
#define ATTN_SMEM (2 * BUF_SZ)   // 71680

// ---------------- qkv smem ----------------------------------------------------
#define QKV_XH 0u
#define QKV_XL 17408u
#define QKV_WH 34816u
#define QKV_WL 69632u
#define QKV_SMEM 104448

extern __shared__ __align__(16) char smem_raw[];

// ---------------- helpers ----------------------------------------------------
__device__ __forceinline__ uint32_t smem_u32(const void* p) {
    uint32_t a;
    asm("{ .reg .u64 t; cvta.to.shared.u64 t, %1; cvt.u32.u64 %0, t; }"
        : "=r"(a) : "l"(p));
    return a;
}
__device__ __forceinline__ float ex2f(float x) {
    float r;
    asm("ex2.approx.f32 %0, %1;" : "=f"(r) : "f"(x));
    return r;
}
__device__ __forceinline__ void cp16(uint32_t dst, const void* src) {
    asm volatile("cp.async.cg.shared.global [%0], [%1], 16;"
                 :: "r"(dst), "l"(src) : "memory");
}
__device__ __forceinline__ void cp_commit() {
    asm volatile("cp.async.commit_group;" ::: "memory");
}
template<int N> __device__ __forceinline__ void cp_wait() {
    asm volatile("cp.async.wait_group %0;" :: "n"(N) : "memory");
}
__device__ __forceinline__ void ldsm4(uint32_t& r0, uint32_t& r1,
                                      uint32_t& r2, uint32_t& r3, uint32_t a) {
    asm volatile("ldmatrix.sync.aligned.m8n8.x4.shared.b16 {%0,%1,%2,%3}, [%4];"
                 : "=r"(r0), "=r"(r1), "=r"(r2), "=r"(r3) : "r"(a));
}
__device__ __forceinline__ void mma_bf16(float* d, const uint32_t* a,
                                         uint32_t b0, uint32_t b1) {
    asm volatile(
        "mma.sync.aligned.m16n8k16.row.col.f32.bf16.bf16.f32 "
        "{%0,%1,%2,%3}, {%4,%5,%6,%7}, {%8,%9}, {%0,%1,%2,%3};"
        : "+f"(d[0]), "+f"(d[1]), "+f"(d[2]), "+f"(d[3])
        : "r"(a[0]), "r"(a[1]), "r"(a[2]), "r"(a[3]), "r"(b0), "r"(b1));
}
__device__ __forceinline__ void mma_f16(float* d, const uint32_t* a,
                                        uint32_t b0, uint32_t b1) {
    asm volatile(
        "mma.sync.aligned.m16n8k16.row.col.f32.f16.f16.f32 "
        "{%0,%1,%2,%3}, {%4,%5,%6,%7}, {%8,%9}, {%0,%1,%2,%3};"
        : "+f"(d[0]), "+f"(d[1]), "+f"(d[2]), "+f"(d[3])
        : "r"(a[0]), "r"(a[1]), "r"(a[2]), "r"(a[3]), "r"(b0), "r"(b1));
}

// ---------------------------------------------------------------------------
// W pre-split: W[p][k][n] fp32 -> W^T hi/lo bf16 [p][n][k]. 192 CTAs x 256 thr.
// ---------------------------------------------------------------------------
__global__ void split_w(const float* __restrict__ Wq,
                        const float* __restrict__ Wk,
                        const float* __restrict__ Wv)
{
    const float* Ws[3] = {Wq, Wk, Wv};
    int idx = blockIdx.x * 256 + threadIdx.x;   // 0..49151
    int p = idx >> 14, r = idx & 16383;
    int n = r >> 7, k = r & 127;
    float v = Ws[p][k * 128 + n];
    __nv_bfloat16 h = __float2bfloat16(v);
    g_wthi[idx] = h;
    g_wtlo[idx] = __float2bfloat16(v - __bfloat162float(h));
}

// ---------------------------------------------------------------------------
// QKV projection, one (row-tile, projection) per CTA. 768 CTAs x 128 thr.
// W prefetch issued first, hidden under x conversion. One MMA pass, one epilogue.
// ---------------------------------------------------------------------------
__global__ __launch_bounds__(128, 2) void qkv_mma(
    const float* __restrict__ x,
    const float* __restrict__ bq, const float* __restrict__ bk,
    const float* __restrict__ bv)
{
    char* smc = smem_raw;
    const uint32_t sb = smem_u32(smc);
    const int tid  = threadIdx.x;
    const int warp = tid >> 5, lane = tid & 31;
    const int g    = lane >> 2, tig = lane & 3;
    const int p    = blockIdx.x >> 8;          // 0..2 : projection
    const int row0 = (blockIdx.x & 255) * 64;  // row-tile
    const int lm_row = ((lane >> 4) << 3) + (lane & 7);
    const int lm_col = ((lane >> 3) & 1) * 16;

    __nv_bfloat16* sxh = reinterpret_cast<__nv_bfloat16*>(smc + QKV_XH);
    __nv_bfloat16* sxl = reinterpret_cast<__nv_bfloat16*>(smc + QKV_XL);

    // 1. issue W^T[p] hi/lo prefetch FIRST (hidden under x conversion below)
    {
        const __nv_bfloat16* wh = g_wthi + (size_t)p * 16384;
        const __nv_bfloat16* wl = g_wtlo + (size_t)p * 16384;
        #pragma unroll
        for (int i = 0; i < 16; i++) {
            int idx = tid + i * 128;
            int r = idx >> 4, q = idx & 15;
            cp16(sb + QKV_WH + r * 272 + q * 16, wh + (size_t)r * 128 + q * 8);
            cp16(sb + QKV_WL + r * 272 + q * 16, wl + (size_t)r * 128 + q * 8);
        }
        cp_commit();
    }

    // 2. x tile -> hi/lo bf16 splits in smem
    #pragma unroll
    for (int i = 0; i < 64; i++) {
        int idx = tid + i * 128;
        int r = idx >> 7, c = idx & 127;
        float v = x[(size_t)row0 * 128 + idx];
        __nv_bfloat16 h = __float2bfloat16(v);
        sxh[r * 136 + c] = h;
        sxl[r * 136 + c] = __float2bfloat16(v - __bfloat162float(h));
    }
    __syncthreads();

    // 3. A fragments (16 rows per warp)
    uint32_t xh[8][4], xl[8][4];
    #pragma unroll
    for (int ks = 0; ks < 8; ks++) {
        int c2 = (ks * 16 + tig * 2) * 2;
        int ra = (warp * 16 + g) * 272, rb = (warp * 16 + g + 8) * 272;
        xh[ks][0] = *(const uint32_t*)(smc + QKV_XH + ra + c2);
        xh[ks][1] = *(const uint32_t*)(smc + QKV_XH + rb + c2);
        xh[ks][2] = *(const uint32_t*)(smc + QKV_XH + ra + c2 + 16);
        xh[ks][3] = *(const uint32_t*)(smc + QKV_XH + rb + c2 + 16);
        xl[ks][0] = *(const uint32_t*)(smc + QKV_XL + ra + c2);
        xl[ks][1] = *(const uint32_t*)(smc + QKV_XL + rb + c2);
        xl[ks][2] = *(const uint32_t*)(smc + QKV_XL + ra + c2 + 16);
        xl[ks][3] = *(const uint32_t*)(smc + QKV_XL + rb + c2 + 16);
    }

    cp_wait<0>();
    __syncthreads();

    // 4. MMA: 3-pass split-bf16 (xh*Wh + xh*Wl + xl*Wh)
    float acc[16][4];
    #pragma unroll
    for (int nb = 0; nb < 16; nb++)
        #pragma unroll
        for (int j = 0; j < 4; j++) acc[nb][j] = 0.f;

    #pragma unroll
    for (int ks = 0; ks < 8; ks++) {
        #pragma unroll
        for (int nbp = 0; nbp < 8; nbp++) {
            uint32_t a = sb + QKV_WH + (uint32_t)(nbp * 16 + lm_row) * 272
                       + ks * 32 + lm_col;
            uint32_t h0, h1, h2, h3, l0_, l1_, l2_, l3_;
            ldsm4(h0, h1, h2, h3, a);
            ldsm4(l0_, l1_, l2_, l3_, a + (QKV_WL - QKV_WH));
            mma_bf16(acc[2*nbp],   xh[ks], h0, h1);
            mma_bf16(acc[2*nbp],   xh[ks], l0_, l1_);
            mma_bf16(acc[2*nbp],   xl[ks], h0, h1);
            mma_bf16(acc[2*nbp+1], xh[ks], h2, h3);
            mma_bf16(acc[2*nbp+1], xh[ks], l2_, l3_);
            mma_bf16(acc[2*nbp+1], xl[ks], h2, h3);
        }
    }

    // 5. epilogue
    const float* bp = (p == 0) ? bq : (p == 1) ? bk : bv;
    const int t0 = row0 + warp * 16 + g;
    if (p < 2) {
        __half* dst = (p == 0) ? g_q16 : g_k16;
        const float sc = (p == 0) ? LOG2E : 1.0f;   // fold log2e into Q
        #pragma unroll
        for (int nb = 0; nb < 16; nb++) {
            int col = nb * 8 + tig * 2;
            float2 bb = *(const float2*)(bp + col);
            __half2 a2;
            a2.x = __float2half_rn((acc[nb][0] + bb.x) * sc);
            a2.y = __float2half_rn((acc[nb][1] + bb.y) * sc);
            __half2 b2;
            b2.x = __float2half_rn((acc[nb][2] + bb.x) * sc);
            b2.y = __float2half_rn((acc[nb][3] + bb.y) * sc);
            *reinterpret_cast<__half2*>(dst + (size_t)t0 * 128 + col) = a2;
            *reinterpret_cast<__half2*>(dst + (size_t)(t0 + 8) * 128 + col) = b2;
        }
    } else {
        // V: stage V^T tile [128 f][64 tokens] in smem (X region reusable
        // once all warps finished fragment loads -> barrier)
        __syncthreads();
        __half* vst = reinterpret_cast<__half*>(smc);
        const int tl = warp * 16 + g;
        #pragma unroll
        for (int nb = 0; nb < 16; nb++) {
            int col = nb * 8 + tig * 2;
            float2 bb = *(const float2*)(bp + col);
            vst[col * 64 + tl]           = __float2half_rn(acc[nb][0] + bb.x);
            vst[(col + 1) * 64 + tl]     = __float2half_rn(acc[nb][1] + bb.y);
            vst[col * 64 + tl + 8]       = __float2half_rn(acc[nb][2] + bb.x);
            vst[(col + 1) * 64 + tl + 8] = __float2half_rn(acc[nb][3] + bb.y);
        }
        __syncthreads();
        // coalesced copy-out: 1024 chunks of 16B
        const int b_ = row0 >> 12, n0 = row0 & 4095;
        #pragma unroll
        for (int i = 0; i < 8; i++) {
            int c = tid + i * 128;
            int f = c >> 3, q = c & 7;
            uint4 v = *reinterpret_cast<uint4*>(vst + f * 64 + q * 8);
            *reinterpret_cast<uint4*>(
                g_vt + ((size_t)b_ * 128 + f) * 4096 + n0 + q * 8) = v;
        }
    }
}

// ---------------------------------------------------------------------------
// attn tile loader (128 threads): KH [64][136]f16 + Vt [128][72]f16.
// ---------------------------------------------------------------------------
__device__ __forceinline__ void load_tiles(uint32_t dstb, int tid,
    const __half* kb_, const __half* vtb, int kt)
{
    const int k0 = kt * BK;
    #pragma unroll
    for (int i = 0; i < 8; i++) {
        int idx = tid + i * 128;           // 0..1023
        int row = idx >> 4, q = idx & 15;  // 64 rows x 16 chunks
        cp16(dstb + OFF_KHI + row * KROW + q * 16,
             kb_ + (size_t)(k0 + row) * NC + q * 8);
    }
    #pragma unroll
    for (int i = 0; i < 8; i++) {
        int idx = tid + i * 128;           // 0..1023
        int row = idx >> 3, q = idx & 7;   // 128 rows x 8 chunks
        cp16(dstb + OFF_VT + row * VROW + q * 16,
             vtb + (size_t)row * NN + k0 + q * 8);
    }
    cp_commit();
}

// ---------------------------------------------------------------------------
// Flash attention (R15 best: R13 loop + ex2 softmax). 256 CTAs, 128 thr.
// ---------------------------------------------------------------------------
__global__ __launch_bounds__(128, 2) void attn_mma(
    const float* __restrict__ x, float* __restrict__ out)
{
    char* smc = smem_raw;
    const uint32_t sb = smem_u32(smc);
    const int tid  = threadIdx.x;
    const int warp = tid >> 5, lane = tid & 31;
    const int g    = lane >> 2, tig = lane & 3;
    const int b    = blockIdx.x >> 6;
    const int q0   = (blockIdx.x & 63) * BQ;
    const int qrow = q0 + warp * 16;
    const int lm_row = ((lane >> 4) << 3) + (lane & 7);
    const int lm_col = ((lane >> 3) & 1) * 16;

    // Q fragments (fp16, pre-scaled), loaded once from global
    uint32_t qh[8][4];
    {
        const uint16_t* qp = (const uint16_t*)g_q16 + ((size_t)b * NN + qrow) * NC;
        #pragma unroll
        for (int ks = 0; ks < 8; ks++) {
            int c = ks * 16 + tig * 2;
            qh[ks][0] = *(const uint32_t*)(qp + (size_t)g * NC + c);
            qh[ks][1] = *(const uint32_t*)(qp + (size_t)(g + 8) * NC + c);
            qh[ks][2] = *(const uint32_t*)(qp + (size_t)g * NC + c + 8);
            qh[ks][3] = *(const uint32_t*)(qp + (size_t)(g + 8) * NC + c + 8);
        }
    }

    const __half* kb_ = g_k16 + (size_t)b * NN * NC;
    const __half* vtb = g_vt  + (size_t)b * NC * NN;

    float O[16][4];
    #pragma unroll
    for (int n = 0; n < 16; n++)
        #pragma unroll
        for (int j = 0; j < 4; j++) O[n][j] = 0.f;
    float m0 = -1e30f, m1 = -1e30f, l0 = 0.f, l1 = 0.f;

    load_tiles(sb, tid, kb_, vtb, 0);

    for (int kt = 0; kt < NIT; kt++) {
        const int cur = kt & 1;
        if (kt + 1 < NIT) {
            load_tiles(sb + (cur ^ 1) * BUF_SZ, tid, kb_, vtb, kt + 1);
            cp_wait<1>();
        } else {
            cp_wait<0>();
        }
        __syncthreads();

        const uint32_t kb = sb + cur * BUF_SZ;

        // ---- S = q16 * k16 : single pass fp16, ldmatrix B-frags ----
        float s[8][4];
        #pragma unroll
        for (int n = 0; n < 8; n++)
            #pragma unroll
            for (int j = 0; j < 4; j++) s[n][j] = 0.f;

        #pragma unroll
        for (int ks = 0; ks < 8; ks++) {
            #pragma unroll
            for (int nbp = 0; nbp < 4; nbp++) {
                uint32_t a = kb + (uint32_t)(nbp * 16 + lm_row) * KROW
                           + ks * 32 + lm_col;
                uint32_t h0, h1, h2, h3;
                ldsm4(h0, h1, h2, h3, a);
                mma_f16(s[2*nbp],   qh[ks], h0, h1);
                mma_f16(s[2*nbp+1], qh[ks], h2, h3);
            }
        }

        // ---- online softmax (log2 domain) ----
        float mx0 = -1e30f, mx1 = -1e30f;
        #pragma unroll
        for (int nb = 0; nb < 8; nb++) {
            mx0 = fmaxf(mx0, fmaxf(s[nb][0], s[nb][1]));
            mx1 = fmaxf(mx1, fmaxf(s[nb][2], s[nb][3]));
        }
        mx0 = fmaxf(mx0, __shfl_xor_sync(0xffffffffu, mx0, 1));
        mx0 = fmaxf(mx0, __shfl_xor_sync(0xffffffffu, mx0, 2));
        mx1 = fmaxf(mx1, __shfl_xor_sync(0xffffffffu, mx1, 1));
        mx1 = fmaxf(mx1, __shfl_xor_sync(0xffffffffu, mx1, 2));

        if (mx0 > m0 || mx1 > m1) {           // conditional rescale
            float mn0 = fmaxf(m0, mx0), mn1 = fmaxf(m1, mx1);
            float sc0 = ex2f(m0 - mn0), sc1 = ex2f(m1 - mn1);
            m0 = mn0; m1 = mn1;
            l0 *= sc0; l1 *= sc1;
            #pragma unroll
            for (int n = 0; n < 16; n++) {
                O[n][0] *= sc0; O[n][1] *= sc0;
                O[n][2] *= sc1; O[n][3] *= sc1;
            }
        }

        // ---- P = 2^(S-m) -> fp16 A-fragments; l from ROUNDED p ----
        uint32_t pf[4][4];
        #pragma unroll
        for (int kk = 0; kk < 4; kk++) {
            #pragma unroll
            for (int h = 0; h < 2; h++) {
                int nb = 2 * kk + h;
                __half2 ha = __floats2half2_rn(ex2f(s[nb][0] - m0),
                                               ex2f(s[nb][1] - m0));
                __half2 hb = __floats2half2_rn(ex2f(s[nb][2] - m1),
                                               ex2f(s[nb][3] - m1));
                float2 fa = __half22float2(ha);
                float2 fb = __half22float2(hb);
                l0 += fa.x + fa.y;
                l1 += fb.x + fb.y;
                pf[kk][0 + h * 2] = *reinterpret_cast<uint32_t*>(&ha);
                pf[kk][1 + h * 2] = *reinterpret_cast<uint32_t*>(&hb);
            }
        }

        // ---- O += P V (fp16), ldmatrix B-frags ----
        const uint32_t vb = kb + OFF_VT;
        #pragma unroll
        for (int kk = 0; kk < 4; kk++) {
            #pragma unroll
            for (int fp = 0; fp < 8; fp++) {
                uint32_t a = vb + (uint32_t)(fp * 16 + lm_row) * VROW
                           + kk * 32 + lm_col;
                uint32_t v0, v1, v2, v3;
                ldsm4(v0, v1, v2, v3, a);
                mma_f16(O[2*fp],   pf[kk], v0, v1);
                mma_f16(O[2*fp+1], pf[kk], v2, v3);
            }
        }
        __syncthreads();
    }

    // ---- epilogue: reduce l over quad, normalize, add residual ----
    l0 += __shfl_xor_sync(0xffffffffu, l0, 1);
    l0 += __shfl_xor_sync(0xffffffffu, l0, 2);
    l1 += __shfl_xor_sync(0xffffffffu, l1, 1);
    l1 += __shfl_xor_sync(0xffffffffu, l1, 2);
    const float inv0 = 1.f / l0, inv1 = 1.f / l1;

    const size_t ra = ((size_t)b * NN + qrow + g) * NC;
    const size_t rb = ((size_t)b * NN + qrow + g + 8) * NC;
    #pragma unroll
    for (int nb2 = 0; nb2 < 16; nb2++) {
        int col = nb2 * 8 + tig * 2;
        float2 xa = *(const float2*)(x + ra + col);
        float2 xb = *(const float2*)(x + rb + col);
        float2 oa = { O[nb2][0] * inv0 + xa.x, O[nb2][1] * inv0 + xa.y };
        float2 ob = { O[nb2][2] * inv1 + xb.x, O[nb2][3] * inv1 + xb.y };
        *(float2*)(out + ra + col) = oa;
        *(float2*)(out + rb + col) = ob;
    }
}

// ---------------------------------------------------------------------------
extern "C" void kernel_launch(void* const* d_in, const int* in_sizes, int n_in,
                              void* d_out, int out_size)
{
    (void)in_sizes; (void)n_in; (void)out_size;
    const float* x  = (const float*)d_in[0];
    const float* Wq = (const float*)d_in[1];
    const float* bq = (const float*)d_in[2];
    const float* Wk = (const float*)d_in[3];
    const float* bk = (const float*)d_in[4];
    const float* Wv = (const float*)d_in[5];
    const float* bv = (const float*)d_in[6];
    float* out = (float*)d_out;

    cudaFuncSetAttribute(qkv_mma,  cudaFuncAttributeMaxDynamicSharedMemorySize, QKV_SMEM);
    cudaFuncSetAttribute(attn_mma, cudaFuncAttributeMaxDynamicSharedMemorySize, ATTN_SMEM);

    split_w<<<192, 256>>>(Wq, Wk, Wv);
    qkv_mma<<<3 * (NB * NN) / 64, 128, QKV_SMEM>>>(x, bq, bk, bv);
    attn_mma<<<NB * (NN / BQ), 128, ATTN_SMEM>>>(x, out);
}